// round 14
// baseline (speedup 1.0000x reference)
#include <cuda_runtime.h>
#include <cuda_fp16.h>
#include <math.h>

#define B_  8
#define C_  64
#define L_  2048
#define H_  4
#define CH_ 16
#define G_  4
#define QT  256     // query tile per attn block (16 warps)

// Scratch (device globals — no allocations allowed)
__device__ float g_p1[256], g_p2[256];   // GN partials (32 groups x 8 splits)
__device__ float g_at[B_*C_*L_];         // attention output, [b][c][L] (proj-coalesced)
// fp16 operands. q scaled by 0.25*log2e. q/k: [bh][l][16]; v: [bh*16+ch][L]
__device__ __half g_qh[B_*H_*L_*CH_];
__device__ __half g_kh[B_*H_*L_*CH_];
__device__ __half g_vt[B_*C_*L_];

__device__ __forceinline__ unsigned ex2h2(unsigned x) {
    unsigned y; asm("ex2.approx.f16x2 %0,%1;" : "=r"(y) : "r"(x)); return y;
}
// D(f32) += A*B  (m16n8k16 fp16)
__device__ __forceinline__ void mma16816(float* d, const unsigned* a, unsigned b0, unsigned b1) {
    asm volatile(
        "mma.sync.aligned.m16n8k16.row.col.f32.f16.f16.f32 "
        "{%0,%1,%2,%3},{%4,%5,%6,%7},{%8,%9},{%0,%1,%2,%3};"
        : "+f"(d[0]), "+f"(d[1]), "+f"(d[2]), "+f"(d[3])
        : "r"(a[0]), "r"(a[1]), "r"(a[2]), "r"(a[3]), "r"(b0), "r"(b1));
}
// D(f16x2) = A*B + C  (m16n8k16 fp16, f16 accumulate)
__device__ __forceinline__ void mma16816h(unsigned* d, const unsigned* a,
                                          unsigned b0, unsigned b1,
                                          unsigned c0, unsigned c1) {
    asm volatile(
        "mma.sync.aligned.m16n8k16.row.col.f16.f16.f16.f16 "
        "{%0,%1},{%2,%3,%4,%5},{%6,%7},{%8,%9};"
        : "=r"(d[0]), "=r"(d[1])
        : "r"(a[0]), "r"(a[1]), "r"(a[2]), "r"(a[3]), "r"(b0), "r"(b1), "r"(c0), "r"(c1));
}
__device__ __forceinline__ void ldmx4(unsigned& r0, unsigned& r1, unsigned& r2, unsigned& r3,
                                      unsigned addr) {
    asm volatile("ldmatrix.sync.aligned.m8n8.x4.shared.b16 {%0,%1,%2,%3},[%4];"
                 : "=r"(r0), "=r"(r1), "=r"(r2), "=r"(r3) : "r"(addr));
}
__device__ __forceinline__ void cpa16(void* dst, const void* src) {
    unsigned d = (unsigned)__cvta_generic_to_shared(dst);
    asm volatile("cp.async.cg.shared.global [%0],[%1],16;" :: "r"(d), "l"(src));
}
__device__ __forceinline__ void cpcommit() { asm volatile("cp.async.commit_group;"); }

// ---------------------------------------------------------------------------
// Kernel 1: GroupNorm partial sums. 256 blocks = 32 groups x 8 splits.
// ---------------------------------------------------------------------------
__global__ __launch_bounds__(256) void gn_part_kernel(const float* __restrict__ x) {
    const float4* base = (const float4*)(x + (size_t)blockIdx.x * 4096);
    float s1 = 0.f, s2 = 0.f;
    #pragma unroll
    for (int i = 0; i < 4; i++) {
        float4 v = base[threadIdx.x + i * 256];
        s1 += v.x + v.y + v.z + v.w;
        s2 += v.x * v.x + v.y * v.y + v.z * v.z + v.w * v.w;
    }
    #pragma unroll
    for (int o = 16; o > 0; o >>= 1) {
        s1 += __shfl_down_sync(0xffffffffu, s1, o);
        s2 += __shfl_down_sync(0xffffffffu, s2, o);
    }
    __shared__ float a1[8], a2[8];
    int w = threadIdx.x >> 5, lane = threadIdx.x & 31;
    if (lane == 0) { a1[w] = s1; a2[w] = s2; }
    __syncthreads();
    if (threadIdx.x == 0) {
        float t1 = 0.f, t2 = 0.f;
        #pragma unroll
        for (int i = 0; i < 8; i++) { t1 += a1[i]; t2 += a2[i]; }
        g_p1[blockIdx.x] = t1;
        g_p2[blockIdx.x] = t2;
    }
}

// ---------------------------------------------------------------------------
// Kernel 2: GN finalize (folded) + GroupNorm-apply + 1x1 conv QKV.
// grid = (L/64, B, 3 parts) = 768 blocks; per-part 64x64 W slice in smem,
// register-tiled 4o x 4l. fp16 packed stores.
// ---------------------------------------------------------------------------
__global__ __launch_bounds__(256) void qkv_kernel(
    const float* __restrict__ x,
    const float* __restrict__ gnw, const float* __restrict__ gnb,
    const float* __restrict__ W,   const float* __restrict__ bias)
{
    __shared__ float WsmT[64][68];    // [c][o] for this part
    __shared__ float xn[64][68];
    __shared__ float sMean[4], sRinv[4];

    int l0   = blockIdx.x * 64;
    int b    = blockIdx.y;
    int part = blockIdx.z;
    int tid  = threadIdx.x;

    if (tid < 4) {                     // fold 8 partials for this batch's 4 groups
        int bg = b * 4 + tid;
        float t1 = 0.f, t2 = 0.f;
        #pragma unroll
        for (int i = 0; i < 8; i++) { t1 += g_p1[bg * 8 + i]; t2 += g_p2[bg * 8 + i]; }
        const float invN = 1.0f / (CH_ * L_);
        float mean = t1 * invN;
        float var  = t2 * invN - mean * mean;
        sMean[tid] = mean;
        sRinv[tid] = rsqrtf(var + 1e-5f);
    }
    __syncthreads();

    for (int i = tid; i < 4096; i += 256) {
        int o = i >> 6, c = i & 63;
        WsmT[c][o] = W[(size_t)part * 4096 + i];
    }
    for (int i = tid; i < 4096; i += 256) {
        int c = i >> 6, l = i & 63;
        int gidx = c >> 4;
        float sc = sRinv[gidx] * gnw[c];
        float sh = gnb[c] - sMean[gidx] * sc;
        xn[c][l] = x[((size_t)(b * C_ + c)) * L_ + l0 + l] * sc + sh;
    }
    __syncthreads();

    const float QSCALE = 0.25f * 1.4426950408889634f;
    int lq = tid & 15, oq = tid >> 4;
    int o0 = oq * 4, lb = lq * 4;
    int head = oq >> 2, ch0 = (oq & 3) * 4;

    float av[4][4];
    #pragma unroll
    for (int oi = 0; oi < 4; oi++)
        #pragma unroll
        for (int li = 0; li < 4; li++) av[oi][li] = 0.f;

    #pragma unroll 8
    for (int c = 0; c < 64; c++) {
        float4 w4 = *(const float4*)&WsmT[c][o0];
        float4 xv = *(const float4*)&xn[c][lb];
        float wv[4] = {w4.x, w4.y, w4.z, w4.w};
        float xl[4] = {xv.x, xv.y, xv.z, xv.w};
        #pragma unroll
        for (int oi = 0; oi < 4; oi++)
            #pragma unroll
            for (int li = 0; li < 4; li++) av[oi][li] += wv[oi] * xl[li];
    }

    float b0 = bias[part * 64 + o0],     b1 = bias[part * 64 + o0 + 1];
    float b2 = bias[part * 64 + o0 + 2], b3 = bias[part * 64 + o0 + 3];

    if (part == 0) {
        #pragma unroll
        for (int li = 0; li < 4; li++) {
            __half2 h01 = __floats2half2_rn((av[0][li] + b0) * QSCALE, (av[1][li] + b1) * QSCALE);
            __half2 h23 = __floats2half2_rn((av[2][li] + b2) * QSCALE, (av[3][li] + b3) * QSCALE);
            uint2 pk; pk.x = *(unsigned*)&h01; pk.y = *(unsigned*)&h23;
            *(uint2*)(g_qh + (((size_t)(b * H_ + head) * L_) + l0 + lb + li) * CH_ + ch0) = pk;
        }
    } else if (part == 1) {
        #pragma unroll
        for (int li = 0; li < 4; li++) {
            __half2 h01 = __floats2half2_rn(av[0][li] + b0, av[1][li] + b1);
            __half2 h23 = __floats2half2_rn(av[2][li] + b2, av[3][li] + b3);
            uint2 pk; pk.x = *(unsigned*)&h01; pk.y = *(unsigned*)&h23;
            *(uint2*)(g_kh + (((size_t)(b * H_ + head) * L_) + l0 + lb + li) * CH_ + ch0) = pk;
        }
    } else {
        float bv[4] = {b0, b1, b2, b3};
        #pragma unroll
        for (int oi = 0; oi < 4; oi++) {
            __half2 ha = __floats2half2_rn(av[oi][0] + bv[oi], av[oi][1] + bv[oi]);
            __half2 hb = __floats2half2_rn(av[oi][2] + bv[oi], av[oi][3] + bv[oi]);
            uint2 pk; pk.x = *(unsigned*)&ha; pk.y = *(unsigned*)&hb;
            *(uint2*)(g_vt + ((size_t)(b * H_ + head) * 16 + ch0 + oi) * L_ + l0 + lb) = pk;
        }
    }
}

// ---------------------------------------------------------------------------
// Kernel 3: flash attention (unchanged from round 13): fp16 tensor cores,
// f16-acc scores seeded -5, ex2.approx.f16x2 in place, 128-key chunks,
// transposed output to g_at[b][c][L]. grid = (L/256, B*H), 512 threads.
// ---------------------------------------------------------------------------
#define KCH 128
__global__ __launch_bounds__(512, 2) void attn_kernel() {
    __shared__ __align__(16) __half Qh[QT][24];        // 12 KB
    __shared__ __align__(16) __half Kh[2][KCH][24];    // 12 KB
    __shared__ __align__(16) __half Vh[2][16][136];    // 8.5 KB (row 272 B)

    int tid  = threadIdx.x;
    int w    = tid >> 5;
    int lane = tid & 31;
    int g    = lane >> 2;
    int t    = lane & 3;
    int bh   = blockIdx.y;
    int qb0  = blockIdx.x * QT;

    const size_t q16 = ((size_t)bh * L_ + qb0) * CH_;
    const size_t k16 = (size_t)bh * L_ * CH_;
    const size_t vr0 = (size_t)bh * CH_ * L_;

    {
        int r = tid >> 1, hf = tid & 1;
        *(uint4*)&Qh[r][hf * 8] = *(const uint4*)(g_qh + q16 + (size_t)r * CH_ + hf * 8);
    }
    __syncwarp();

    auto stage = [&](int s0, int st) {
        if (tid < 256) {
            int key = tid >> 1, hf = tid & 1;
            cpa16(&Kh[st][key][hf * 8], g_kh + k16 + (size_t)(s0 + key) * CH_ + hf * 8);
        } else {
            int r = tid - 256, ch = r >> 4, seg = r & 15;
            cpa16(&Vh[st][ch][seg * 8], g_vt + vr0 + (size_t)ch * L_ + s0 + seg * 8);
        }
    };

    stage(0, 0);
    cpcommit();

    const unsigned* Qh32 = (const unsigned*)Qh;
    int qr = w * 16;
    unsigned aQ[4];
    aQ[0] = Qh32[(qr + g    ) * 12 + t];
    aQ[1] = Qh32[(qr + g + 8) * 12 + t];
    aQ[2] = Qh32[(qr + g    ) * 12 + t + 4];
    aQ[3] = Qh32[(qr + g + 8) * 12 + t + 4];

    int lr = lane & 7, quad = lane >> 3;
    unsigned laneK = (unsigned)(((quad >> 1) * 8 + lr) * 48 + (quad & 1) * 16);
    unsigned laneV = (unsigned)(lr * 272 + quad * 16);
    unsigned baseK = (unsigned)__cvta_generic_to_shared(&Kh[0][0][0]) + laneK;
    unsigned baseV = (unsigned)__cvta_generic_to_shared(&Vh[0][0][0]) + laneV;

    const unsigned SEED = 0xC500C500u;   // half2(-5,-5): constant softmax shift

    float o0[4] = {0,0,0,0}, o1[4] = {0,0,0,0};
    float rs0 = 0.f, rs1 = 0.f;

    for (int c = 0; c < L_ / KCH; c++) {
        if (c < L_ / KCH - 1) { stage((c + 1) * KCH, (c + 1) & 1); cpcommit(); }
        if (c < L_ / KCH - 1) asm volatile("cp.async.wait_group 1;");
        else                  asm volatile("cp.async.wait_group 0;");
        __syncthreads();

        int st = c & 1;
        unsigned kb = baseK + st * 6144;   // 128*48
        unsigned vb = baseV + st * 4352;   // 16*272

        #pragma unroll
        for (int kp = 0; kp < 4; kp++) {
            unsigned bKa[4], bKb[4], vA[4], vB[4];
            ldmx4(bKa[0], bKa[1], bKa[2], bKa[3], kb + (2 * kp    ) * 768);
            ldmx4(bKb[0], bKb[1], bKb[2], bKb[3], kb + (2 * kp + 1) * 768);
            ldmx4(vA[0], vA[1], vA[2], vA[3], vb +        kp * 64);
            ldmx4(vB[0], vB[1], vB[2], vB[3], vb + 2176 + kp * 64);

            unsigned sd0[2], sd1[2], sd2[2], sd3[2];
            mma16816h(sd0, aQ, bKa[0], bKa[1], SEED, SEED);
            mma16816h(sd1, aQ, bKa[2], bKa[3], SEED, SEED);
            mma16816h(sd2, aQ, bKb[0], bKb[1], SEED, SEED);
            mma16816h(sd3, aQ, bKb[2], bKb[3], SEED, SEED);

            unsigned aP[4];
            aP[0] = ex2h2(sd0[0]); aP[1] = ex2h2(sd0[1]);
            aP[2] = ex2h2(sd1[0]); aP[3] = ex2h2(sd1[1]);
            {
                __half2 he = __hadd2(*(__half2*)&aP[0], *(__half2*)&aP[2]);
                __half2 ho = __hadd2(*(__half2*)&aP[1], *(__half2*)&aP[3]);
                float2 fe = __half22float2(he);
                float2 fo = __half22float2(ho);
                rs0 += fe.x + fe.y;
                rs1 += fo.x + fo.y;
            }
            mma16816(o0, aP, vA[0], vA[1]);
            mma16816(o1, aP, vB[0], vB[1]);

            aP[0] = ex2h2(sd2[0]); aP[1] = ex2h2(sd2[1]);
            aP[2] = ex2h2(sd3[0]); aP[3] = ex2h2(sd3[1]);
            {
                __half2 he = __hadd2(*(__half2*)&aP[0], *(__half2*)&aP[2]);
                __half2 ho = __hadd2(*(__half2*)&aP[1], *(__half2*)&aP[3]);
                float2 fe = __half22float2(he);
                float2 fo = __half22float2(ho);
                rs0 += fe.x + fe.y;
                rs1 += fo.x + fo.y;
            }
            mma16816(o0, aP, vA[2], vA[3]);
            mma16816(o1, aP, vB[2], vB[3]);
        }
        __syncthreads();
    }

    rs0 += __shfl_xor_sync(0xffffffffu, rs0, 1);
    rs0 += __shfl_xor_sync(0xffffffffu, rs0, 2);
    rs1 += __shfl_xor_sync(0xffffffffu, rs1, 1);
    rs1 += __shfl_xor_sync(0xffffffffu, rs1, 2);
    float inv0 = 1.0f / rs0, inv1 = 1.0f / rs1;

    int pos0 = qb0 + w * 16 + g, pos1 = pos0 + 8;
    #pragma unroll
    for (int ct = 0; ct < 2; ct++) {
        float* oacc = ct ? o1 : o0;
        int cc = ct * 8 + 2 * t;
        size_t r0 = ((size_t)bh * 16 + cc) * L_;
        size_t r1 = ((size_t)bh * 16 + cc + 1) * L_;
        g_at[r0 + pos0] = oacc[0] * inv0;
        g_at[r1 + pos0] = oacc[1] * inv0;
        g_at[r0 + pos1] = oacc[2] * inv1;
        g_at[r1 + pos1] = oacc[3] * inv1;
    }
}

// ---------------------------------------------------------------------------
// Kernel 4: 1x1 conv proj + residual. grid = (L/32, B) = 512 blocks,
// 256 threads, 2o x 4l per thread. Coalesced float4 stage from g_at.
// ---------------------------------------------------------------------------
__global__ __launch_bounds__(256) void proj_kernel(
    const float* __restrict__ x,
    const float* __restrict__ P, const float* __restrict__ pb,
    float* __restrict__ out)
{
    __shared__ float PsmT[64][68];
    __shared__ float asm_[64][36];   // [c][l 0..31]

    int l0 = blockIdx.x * 32;
    int b  = blockIdx.y;
    int tid = threadIdx.x;

    for (int i = tid; i < 4096; i += 256) {
        int o = i >> 6, c = i & 63;
        PsmT[c][o] = P[i];
    }
    for (int i = tid; i < 512; i += 256) {
        int c = i >> 3, seg = i & 7;
        *(float4*)&asm_[c][seg * 4] =
            *(const float4*)(g_at + ((size_t)(b * C_ + c)) * L_ + l0 + seg * 4);
    }
    __syncthreads();

    int lq = tid & 7, oq = tid >> 3;   // lq 0..7, oq 0..31
    int o0 = oq * 2, lb = lq * 4;

    float4 av[2];
    av[0] = make_float4(0.f, 0.f, 0.f, 0.f);
    av[1] = av[0];

    #pragma unroll 8
    for (int c = 0; c < 64; c++) {
        float2 w2 = *(const float2*)&PsmT[c][o0];
        float4 xv = *(const float4*)&asm_[c][lb];
        av[0].x += w2.x * xv.x; av[0].y += w2.x * xv.y; av[0].z += w2.x * xv.z; av[0].w += w2.x * xv.w;
        av[1].x += w2.y * xv.x; av[1].y += w2.y * xv.y; av[1].z += w2.y * xv.z; av[1].w += w2.y * xv.w;
    }

    #pragma unroll
    for (int oi = 0; oi < 2; oi++) {
        int o = o0 + oi;
        float bo = pb[o];
        size_t idx = ((size_t)(b * C_ + o)) * L_ + l0 + lb;
        float4 xr = *(const float4*)(x + idx);
        float4 r;
        r.x = xr.x + av[oi].x + bo;
        r.y = xr.y + av[oi].y + bo;
        r.z = xr.z + av[oi].z + bo;
        r.w = xr.w + av[oi].w + bo;
        *(float4*)(out + idx) = r;
    }
}

// ---------------------------------------------------------------------------
extern "C" void kernel_launch(void* const* d_in, const int* in_sizes, int n_in,
                              void* d_out, int out_size) {
    const float* x    = (const float*)d_in[0];
    const float* gnw  = (const float*)d_in[1];
    const float* gnb  = (const float*)d_in[2];
    const float* qkvw = (const float*)d_in[3];
    const float* qkvb = (const float*)d_in[4];
    const float* pw   = (const float*)d_in[5];
    const float* pb   = (const float*)d_in[6];
    float* out = (float*)d_out;

    gn_part_kernel<<<256, 256>>>(x);
    qkv_kernel<<<dim3(L_ / 64, B_, 3), 256>>>(x, gnw, gnb, qkvw, qkvb);
    attn_kernel<<<dim3(L_ / QT, B_ * H_), 512>>>();
    proj_kernel<<<dim3(L_ / 32, B_), 256>>>(x, pw, pb, out);
}

// round 15
// speedup vs baseline: 1.0310x; 1.0310x over previous
#include <cuda_runtime.h>
#include <cuda_fp16.h>
#include <math.h>

#define B_  8
#define C_  64
#define L_  2048
#define H_  4
#define CH_ 16
#define G_  4
#define QT  256     // query tile per attn block (16 warps)

// Scratch (device globals — no allocations allowed)
__device__ float g_p1[256], g_p2[256];   // GN partials (32 groups x 8 splits)
__device__ float g_at[B_*C_*L_];         // attention output, [b][c][L] (proj-coalesced)
// fp16 operands. q scaled by 0.25*log2e. q/k: [bh][l][16]; v: [bh*16+ch][L]
__device__ __half g_qh[B_*H_*L_*CH_];
__device__ __half g_kh[B_*H_*L_*CH_];
__device__ __half g_vt[B_*C_*L_];

__device__ __forceinline__ unsigned ex2h2(unsigned x) {
    unsigned y; asm("ex2.approx.f16x2 %0,%1;" : "=r"(y) : "r"(x)); return y;
}
// D(f32) += A*B  (m16n8k16 fp16)
__device__ __forceinline__ void mma16816(float* d, const unsigned* a, unsigned b0, unsigned b1) {
    asm volatile(
        "mma.sync.aligned.m16n8k16.row.col.f32.f16.f16.f32 "
        "{%0,%1,%2,%3},{%4,%5,%6,%7},{%8,%9},{%0,%1,%2,%3};"
        : "+f"(d[0]), "+f"(d[1]), "+f"(d[2]), "+f"(d[3])
        : "r"(a[0]), "r"(a[1]), "r"(a[2]), "r"(a[3]), "r"(b0), "r"(b1));
}
// D(f16x2) = A*B + C  (m16n8k16 fp16, f16 accumulate)
__device__ __forceinline__ void mma16816h(unsigned* d, const unsigned* a,
                                          unsigned b0, unsigned b1,
                                          unsigned c0, unsigned c1) {
    asm volatile(
        "mma.sync.aligned.m16n8k16.row.col.f16.f16.f16.f16 "
        "{%0,%1},{%2,%3,%4,%5},{%6,%7},{%8,%9};"
        : "=r"(d[0]), "=r"(d[1])
        : "r"(a[0]), "r"(a[1]), "r"(a[2]), "r"(a[3]), "r"(b0), "r"(b1), "r"(c0), "r"(c1));
}
__device__ __forceinline__ void ldmx4(unsigned& r0, unsigned& r1, unsigned& r2, unsigned& r3,
                                      unsigned addr) {
    asm volatile("ldmatrix.sync.aligned.m8n8.x4.shared.b16 {%0,%1,%2,%3},[%4];"
                 : "=r"(r0), "=r"(r1), "=r"(r2), "=r"(r3) : "r"(addr));
}
__device__ __forceinline__ void cpa16(void* dst, const void* src) {
    unsigned d = (unsigned)__cvta_generic_to_shared(dst);
    asm volatile("cp.async.cg.shared.global [%0],[%1],16;" :: "r"(d), "l"(src));
}
__device__ __forceinline__ void cpcommit() { asm volatile("cp.async.commit_group;"); }

// ---------------------------------------------------------------------------
// Kernel 1: GroupNorm partial sums. 256 blocks = 32 groups x 8 splits.
// ---------------------------------------------------------------------------
__global__ __launch_bounds__(256) void gn_part_kernel(const float* __restrict__ x) {
    const float4* base = (const float4*)(x + (size_t)blockIdx.x * 4096);
    float s1 = 0.f, s2 = 0.f;
    #pragma unroll
    for (int i = 0; i < 4; i++) {
        float4 v = base[threadIdx.x + i * 256];
        s1 += v.x + v.y + v.z + v.w;
        s2 += v.x * v.x + v.y * v.y + v.z * v.z + v.w * v.w;
    }
    #pragma unroll
    for (int o = 16; o > 0; o >>= 1) {
        s1 += __shfl_down_sync(0xffffffffu, s1, o);
        s2 += __shfl_down_sync(0xffffffffu, s2, o);
    }
    __shared__ float a1[8], a2[8];
    int w = threadIdx.x >> 5, lane = threadIdx.x & 31;
    if (lane == 0) { a1[w] = s1; a2[w] = s2; }
    __syncthreads();
    if (threadIdx.x == 0) {
        float t1 = 0.f, t2 = 0.f;
        #pragma unroll
        for (int i = 0; i < 8; i++) { t1 += a1[i]; t2 += a2[i]; }
        g_p1[blockIdx.x] = t1;
        g_p2[blockIdx.x] = t2;
    }
}

// ---------------------------------------------------------------------------
// Kernel 2: GN finalize (folded) + GroupNorm-apply + 1x1 conv QKV.
// grid = (L/64, B, 3 parts) = 768 blocks; per-part 64x64 W slice in smem,
// register-tiled 4o x 4l. fp16 packed stores.
// ---------------------------------------------------------------------------
__global__ __launch_bounds__(256) void qkv_kernel(
    const float* __restrict__ x,
    const float* __restrict__ gnw, const float* __restrict__ gnb,
    const float* __restrict__ W,   const float* __restrict__ bias)
{
    __shared__ float WsmT[64][68];    // [c][o] for this part
    __shared__ float xn[64][68];
    __shared__ float sMean[4], sRinv[4];

    int l0   = blockIdx.x * 64;
    int b    = blockIdx.y;
    int part = blockIdx.z;
    int tid  = threadIdx.x;

    if (tid < 4) {                     // fold 8 partials for this batch's 4 groups
        int bg = b * 4 + tid;
        float t1 = 0.f, t2 = 0.f;
        #pragma unroll
        for (int i = 0; i < 8; i++) { t1 += g_p1[bg * 8 + i]; t2 += g_p2[bg * 8 + i]; }
        const float invN = 1.0f / (CH_ * L_);
        float mean = t1 * invN;
        float var  = t2 * invN - mean * mean;
        sMean[tid] = mean;
        sRinv[tid] = rsqrtf(var + 1e-5f);
    }
    __syncthreads();

    for (int i = tid; i < 4096; i += 256) {
        int o = i >> 6, c = i & 63;
        WsmT[c][o] = W[(size_t)part * 4096 + i];
    }
    for (int i = tid; i < 4096; i += 256) {
        int c = i >> 6, l = i & 63;
        int gidx = c >> 4;
        float sc = sRinv[gidx] * gnw[c];
        float sh = gnb[c] - sMean[gidx] * sc;
        xn[c][l] = x[((size_t)(b * C_ + c)) * L_ + l0 + l] * sc + sh;
    }
    __syncthreads();

    const float QSCALE = 0.25f * 1.4426950408889634f;
    int lq = tid & 15, oq = tid >> 4;
    int o0 = oq * 4, lb = lq * 4;
    int head = oq >> 2, ch0 = (oq & 3) * 4;

    float av[4][4];
    #pragma unroll
    for (int oi = 0; oi < 4; oi++)
        #pragma unroll
        for (int li = 0; li < 4; li++) av[oi][li] = 0.f;

    #pragma unroll 8
    for (int c = 0; c < 64; c++) {
        float4 w4 = *(const float4*)&WsmT[c][o0];
        float4 xv = *(const float4*)&xn[c][lb];
        float wv[4] = {w4.x, w4.y, w4.z, w4.w};
        float xl[4] = {xv.x, xv.y, xv.z, xv.w};
        #pragma unroll
        for (int oi = 0; oi < 4; oi++)
            #pragma unroll
            for (int li = 0; li < 4; li++) av[oi][li] += wv[oi] * xl[li];
    }

    float b0 = bias[part * 64 + o0],     b1 = bias[part * 64 + o0 + 1];
    float b2 = bias[part * 64 + o0 + 2], b3 = bias[part * 64 + o0 + 3];

    if (part == 0) {
        #pragma unroll
        for (int li = 0; li < 4; li++) {
            __half2 h01 = __floats2half2_rn((av[0][li] + b0) * QSCALE, (av[1][li] + b1) * QSCALE);
            __half2 h23 = __floats2half2_rn((av[2][li] + b2) * QSCALE, (av[3][li] + b3) * QSCALE);
            uint2 pk; pk.x = *(unsigned*)&h01; pk.y = *(unsigned*)&h23;
            *(uint2*)(g_qh + (((size_t)(b * H_ + head) * L_) + l0 + lb + li) * CH_ + ch0) = pk;
        }
    } else if (part == 1) {
        #pragma unroll
        for (int li = 0; li < 4; li++) {
            __half2 h01 = __floats2half2_rn(av[0][li] + b0, av[1][li] + b1);
            __half2 h23 = __floats2half2_rn(av[2][li] + b2, av[3][li] + b3);
            uint2 pk; pk.x = *(unsigned*)&h01; pk.y = *(unsigned*)&h23;
            *(uint2*)(g_kh + (((size_t)(b * H_ + head) * L_) + l0 + lb + li) * CH_ + ch0) = pk;
        }
    } else {
        float bv[4] = {b0, b1, b2, b3};
        #pragma unroll
        for (int oi = 0; oi < 4; oi++) {
            __half2 ha = __floats2half2_rn(av[oi][0] + bv[oi], av[oi][1] + bv[oi]);
            __half2 hb = __floats2half2_rn(av[oi][2] + bv[oi], av[oi][3] + bv[oi]);
            uint2 pk; pk.x = *(unsigned*)&ha; pk.y = *(unsigned*)&hb;
            *(uint2*)(g_vt + ((size_t)(b * H_ + head) * 16 + ch0 + oi) * L_ + l0 + lb) = pk;
        }
    }
}

// ---------------------------------------------------------------------------
// Kernel 3: flash attention (unchanged): fp16 tensor cores, f16-acc scores
// seeded -5, ex2.approx.f16x2 in place, 128-key chunks, transposed output
// to g_at[b][c][L]. grid = (L/256, B*H), 512 threads.
// ---------------------------------------------------------------------------
#define KCH 128
__global__ __launch_bounds__(512, 2) void attn_kernel() {
    __shared__ __align__(16) __half Qh[QT][24];        // 12 KB
    __shared__ __align__(16) __half Kh[2][KCH][24];    // 12 KB
    __shared__ __align__(16) __half Vh[2][16][136];    // 8.5 KB (row 272 B)

    int tid  = threadIdx.x;
    int w    = tid >> 5;
    int lane = tid & 31;
    int g    = lane >> 2;
    int t    = lane & 3;
    int bh   = blockIdx.y;
    int qb0  = blockIdx.x * QT;

    const size_t q16 = ((size_t)bh * L_ + qb0) * CH_;
    const size_t k16 = (size_t)bh * L_ * CH_;
    const size_t vr0 = (size_t)bh * CH_ * L_;

    {
        int r = tid >> 1, hf = tid & 1;
        *(uint4*)&Qh[r][hf * 8] = *(const uint4*)(g_qh + q16 + (size_t)r * CH_ + hf * 8);
    }
    __syncwarp();

    auto stage = [&](int s0, int st) {
        if (tid < 256) {
            int key = tid >> 1, hf = tid & 1;
            cpa16(&Kh[st][key][hf * 8], g_kh + k16 + (size_t)(s0 + key) * CH_ + hf * 8);
        } else {
            int r = tid - 256, ch = r >> 4, seg = r & 15;
            cpa16(&Vh[st][ch][seg * 8], g_vt + vr0 + (size_t)ch * L_ + s0 + seg * 8);
        }
    };

    stage(0, 0);
    cpcommit();

    const unsigned* Qh32 = (const unsigned*)Qh;
    int qr = w * 16;
    unsigned aQ[4];
    aQ[0] = Qh32[(qr + g    ) * 12 + t];
    aQ[1] = Qh32[(qr + g + 8) * 12 + t];
    aQ[2] = Qh32[(qr + g    ) * 12 + t + 4];
    aQ[3] = Qh32[(qr + g + 8) * 12 + t + 4];

    int lr = lane & 7, quad = lane >> 3;
    unsigned laneK = (unsigned)(((quad >> 1) * 8 + lr) * 48 + (quad & 1) * 16);
    unsigned laneV = (unsigned)(lr * 272 + quad * 16);
    unsigned baseK = (unsigned)__cvta_generic_to_shared(&Kh[0][0][0]) + laneK;
    unsigned baseV = (unsigned)__cvta_generic_to_shared(&Vh[0][0][0]) + laneV;

    const unsigned SEED = 0xC500C500u;   // half2(-5,-5): constant softmax shift

    float o0[4] = {0,0,0,0}, o1[4] = {0,0,0,0};
    float rs0 = 0.f, rs1 = 0.f;

    for (int c = 0; c < L_ / KCH; c++) {
        if (c < L_ / KCH - 1) { stage((c + 1) * KCH, (c + 1) & 1); cpcommit(); }
        if (c < L_ / KCH - 1) asm volatile("cp.async.wait_group 1;");
        else                  asm volatile("cp.async.wait_group 0;");
        __syncthreads();

        int st = c & 1;
        unsigned kb = baseK + st * 6144;   // 128*48
        unsigned vb = baseV + st * 4352;   // 16*272

        #pragma unroll
        for (int kp = 0; kp < 4; kp++) {
            unsigned bKa[4], bKb[4], vA[4], vB[4];
            ldmx4(bKa[0], bKa[1], bKa[2], bKa[3], kb + (2 * kp    ) * 768);
            ldmx4(bKb[0], bKb[1], bKb[2], bKb[3], kb + (2 * kp + 1) * 768);
            ldmx4(vA[0], vA[1], vA[2], vA[3], vb +        kp * 64);
            ldmx4(vB[0], vB[1], vB[2], vB[3], vb + 2176 + kp * 64);

            unsigned sd0[2], sd1[2], sd2[2], sd3[2];
            mma16816h(sd0, aQ, bKa[0], bKa[1], SEED, SEED);
            mma16816h(sd1, aQ, bKa[2], bKa[3], SEED, SEED);
            mma16816h(sd2, aQ, bKb[0], bKb[1], SEED, SEED);
            mma16816h(sd3, aQ, bKb[2], bKb[3], SEED, SEED);

            unsigned aP[4];
            aP[0] = ex2h2(sd0[0]); aP[1] = ex2h2(sd0[1]);
            aP[2] = ex2h2(sd1[0]); aP[3] = ex2h2(sd1[1]);
            {
                __half2 he = __hadd2(*(__half2*)&aP[0], *(__half2*)&aP[2]);
                __half2 ho = __hadd2(*(__half2*)&aP[1], *(__half2*)&aP[3]);
                float2 fe = __half22float2(he);
                float2 fo = __half22float2(ho);
                rs0 += fe.x + fe.y;
                rs1 += fo.x + fo.y;
            }
            mma16816(o0, aP, vA[0], vA[1]);
            mma16816(o1, aP, vB[0], vB[1]);

            aP[0] = ex2h2(sd2[0]); aP[1] = ex2h2(sd2[1]);
            aP[2] = ex2h2(sd3[0]); aP[3] = ex2h2(sd3[1]);
            {
                __half2 he = __hadd2(*(__half2*)&aP[0], *(__half2*)&aP[2]);
                __half2 ho = __hadd2(*(__half2*)&aP[1], *(__half2*)&aP[3]);
                float2 fe = __half22float2(he);
                float2 fo = __half22float2(ho);
                rs0 += fe.x + fe.y;
                rs1 += fo.x + fo.y;
            }
            mma16816(o0, aP, vA[2], vA[3]);
            mma16816(o1, aP, vB[2], vB[3]);
        }
        __syncthreads();
    }

    rs0 += __shfl_xor_sync(0xffffffffu, rs0, 1);
    rs0 += __shfl_xor_sync(0xffffffffu, rs0, 2);
    rs1 += __shfl_xor_sync(0xffffffffu, rs1, 1);
    rs1 += __shfl_xor_sync(0xffffffffu, rs1, 2);
    float inv0 = 1.0f / rs0, inv1 = 1.0f / rs1;

    int pos0 = qb0 + w * 16 + g, pos1 = pos0 + 8;
    #pragma unroll
    for (int ct = 0; ct < 2; ct++) {
        float* oacc = ct ? o1 : o0;
        int cc = ct * 8 + 2 * t;
        size_t r0 = ((size_t)bh * 16 + cc) * L_;
        size_t r1 = ((size_t)bh * 16 + cc + 1) * L_;
        g_at[r0 + pos0] = oacc[0] * inv0;
        g_at[r1 + pos0] = oacc[1] * inv0;
        g_at[r0 + pos1] = oacc[2] * inv1;
        g_at[r1 + pos1] = oacc[3] * inv1;
    }
}

// ---------------------------------------------------------------------------
// Kernel 4: 1x1 conv proj + residual. grid = (L/64, B, 2 o-splits) = 512
// blocks, 256 threads. Each block: 32x64 P half-slice (8 KB, LDG->STS) +
// full 64x64 A tile (cp.async), x residual preloaded into regs up front.
// Inner GEMM + accumulation order identical to before.
// ---------------------------------------------------------------------------
__global__ __launch_bounds__(256) void proj_kernel(
    const float* __restrict__ x,
    const float* __restrict__ P, const float* __restrict__ pb,
    float* __restrict__ out)
{
    __shared__ float PsmT[64][36];   // [c][o 0..31] for this o-split
    __shared__ float asm_[64][68];   // [c][l 0..63]

    int l0  = blockIdx.x * 64;
    int b   = blockIdx.y;
    int os  = blockIdx.z;            // output half: o in [os*32, os*32+32)
    int tid = threadIdx.x;

    // A stage via cp.async: 64 rows x 16 segs of 16B = 1024 transfers, 4/thread
    for (int i = tid; i < 1024; i += 256) {
        int c = i >> 4, seg = i & 15;
        cpa16(&asm_[c][seg * 4], g_at + ((size_t)(b * C_ + c)) * L_ + l0 + seg * 4);
    }
    cpcommit();

    // x residual preload (consumed at the very end; latency hidden by stage+GEMM)
    int lq = tid & 15, oq = tid >> 4;      // oq 0..15
    int o0 = os * 32 + oq * 2, lb = lq * 4;
    size_t idx0 = ((size_t)(b * C_ + o0)) * L_ + l0 + lb;
    size_t idx1 = idx0 + L_;
    float4 xr0 = *(const float4*)(x + idx0);
    float4 xr1 = *(const float4*)(x + idx1);
    float bo0 = pb[o0], bo1 = pb[o0 + 1];

    // P half-slice stage (transposed): 2048 elems, 8/thread
    for (int i = tid; i < 2048; i += 256) {
        int o = i >> 6, c = i & 63;
        PsmT[c][o] = P[(size_t)(os * 32 + o) * 64 + c];
    }
    asm volatile("cp.async.wait_group 0;");
    __syncthreads();

    float4 av[2];
    av[0] = make_float4(0.f, 0.f, 0.f, 0.f);
    av[1] = av[0];

    #pragma unroll 8
    for (int c = 0; c < 64; c++) {
        float2 w2 = *(const float2*)&PsmT[c][oq * 2];
        float4 xv = *(const float4*)&asm_[c][lb];
        av[0].x += w2.x * xv.x; av[0].y += w2.x * xv.y; av[0].z += w2.x * xv.z; av[0].w += w2.x * xv.w;
        av[1].x += w2.y * xv.x; av[1].y += w2.y * xv.y; av[1].z += w2.y * xv.z; av[1].w += w2.y * xv.w;
    }

    float4 r0, r1;
    r0.x = xr0.x + av[0].x + bo0;
    r0.y = xr0.y + av[0].y + bo0;
    r0.z = xr0.z + av[0].z + bo0;
    r0.w = xr0.w + av[0].w + bo0;
    r1.x = xr1.x + av[1].x + bo1;
    r1.y = xr1.y + av[1].y + bo1;
    r1.z = xr1.z + av[1].z + bo1;
    r1.w = xr1.w + av[1].w + bo1;
    *(float4*)(out + idx0) = r0;
    *(float4*)(out + idx1) = r1;
}

// ---------------------------------------------------------------------------
extern "C" void kernel_launch(void* const* d_in, const int* in_sizes, int n_in,
                              void* d_out, int out_size) {
    const float* x    = (const float*)d_in[0];
    const float* gnw  = (const float*)d_in[1];
    const float* gnb  = (const float*)d_in[2];
    const float* qkvw = (const float*)d_in[3];
    const float* qkvb = (const float*)d_in[4];
    const float* pw   = (const float*)d_in[5];
    const float* pb   = (const float*)d_in[6];
    float* out = (float*)d_out;

    gn_part_kernel<<<256, 256>>>(x);
    qkv_kernel<<<dim3(L_ / 64, B_, 3), 256>>>(x, gnw, gnb, qkvw, qkvb);
    attn_kernel<<<dim3(L_ / QT, B_ * H_), 512>>>();
    proj_kernel<<<dim3(L_ / 64, B_, 2), 256>>>(x, pw, pb, out);
}